// round 11
// baseline (speedup 1.0000x reference)
#include <cuda_runtime.h>
#include <math.h>

// Problem constants (match reference)
#define FF       20
#define V_FIELD  5000
#define TOTALV   (FF * V_FIELD)     // 100000
#define DD       64
#define BB       8192
#define NPAIRS   190

#define WARPS_PER_BLOCK  4
#define NBLOCKS          (BB / WARPS_PER_BLOCK)  // 2048

// Sample-major single kernel. R11 = R10 + 2-pair/4-load batching with __ldg
// KEPT (R8's regression confounded batching with __ldcg L1-bypass; L1 is 59%
// busy doing real work). __launch_bounds__(128, 12) pins regs ~42 so
// occupancy stays ~48 warps/SM while per-warp outstanding loads double
// (MLP_p1 ~2 -> ~4). Discriminates latency-bound (expect ~66-68us) vs
// LTS-cap-bound (expect neutral ~71.5us).
__global__ void __launch_bounds__(WARPS_PER_BLOCK * 32, 12)
ffm_all(const int* __restrict__ x, const float* __restrict__ W,
        const float* __restrict__ Wl, const float* __restrict__ bias,
        float* __restrict__ out) {
    // Pair metadata: {i, j, baseA, baseB}; bases in float2 units.
    __shared__ int4 meta[NPAIRS];
    for (int p = threadIdx.x; p < NPAIRS; p += blockDim.x) {
        int i = 0, rem = p;
        while (rem >= FF - 1 - i) { rem -= FF - 1 - i; i++; }
        const int j = i + 1 + rem;
        // a = W[j, i*V_FIELD + xi], b = W[i, j*V_FIELD + xj]
        meta[p] = make_int4(i, j,
                            (j * TOTALV + i * V_FIELD) * (DD / 2),
                            (i * TOTALV + j * V_FIELD) * (DD / 2));
    }
    __syncthreads();

    const int lane = threadIdx.x & 31;
    const int w    = threadIdx.x >> 5;
    const int s    = blockIdx.x * WARPS_PER_BLOCK + w;
    const float2* __restrict__ W2 = (const float2*)W;

    // Index row across lanes; lanes < FF seed the linear term, then the
    // index is pre-scaled to float2-row units (x32).
    int   xv  = 0;
    float lin = 0.f;
    if (lane < FF) {
        xv  = x[s * FF + lane];
        lin = __ldg(&Wl[lane * V_FIELD + xv]);
        xv *= (DD / 2);
    }

    float acc0 = lin, acc1 = 0.f;
    #pragma unroll 5
    for (int q = 0; q < NPAIRS; q += 2) {
        const int4 m0 = meta[q];
        const int4 m1 = meta[q + 1];
        // All four addresses first (1 IADD each after the shfl)...
        const unsigned a0 = (unsigned)(m0.z + __shfl_sync(0xffffffffu, xv, m0.x)) + lane;
        const unsigned b0 = (unsigned)(m0.w + __shfl_sync(0xffffffffu, xv, m0.y)) + lane;
        const unsigned a1 = (unsigned)(m1.z + __shfl_sync(0xffffffffu, xv, m1.x)) + lane;
        const unsigned b1 = (unsigned)(m1.w + __shfl_sync(0xffffffffu, xv, m1.y)) + lane;
        // ...then four independent 256B row loads (L1-allocating)...
        const float2 av0 = __ldg(W2 + a0);
        const float2 bv0 = __ldg(W2 + b0);
        const float2 av1 = __ldg(W2 + a1);
        const float2 bv1 = __ldg(W2 + b1);
        // ...then the math on two independent accumulator chains.
        acc0 = fmaf(av0.x, bv0.x, acc0);
        acc0 = fmaf(av0.y, bv0.y, acc0);
        acc1 = fmaf(av1.x, bv1.x, acc1);
        acc1 = fmaf(av1.y, bv1.y, acc1);
    }

    float acc = acc0 + acc1;
    #pragma unroll
    for (int o = 16; o; o >>= 1)
        acc += __shfl_xor_sync(0xffffffffu, acc, o);
    if (lane == 0) {
        const float z = acc + bias[0];
        out[s] = 1.f / (1.f + __expf(-z));
    }
}

extern "C" void kernel_launch(void* const* d_in, const int* in_sizes, int n_in,
                              void* d_out, int out_size) {
    const int*   x    = (const int*)d_in[0];
    const float* W    = (const float*)d_in[1];
    const float* Wl   = (const float*)d_in[2];
    const float* bias = (const float*)d_in[3];
    float*       out  = (float*)d_out;

    ffm_all<<<NBLOCKS, WARPS_PER_BLOCK * 32>>>(x, W, Wl, bias, out);
}

// round 12
// speedup vs baseline: 1.2270x; 1.2270x over previous
#include <cuda_runtime.h>
#include <math.h>

// Problem constants (match reference)
#define FF       20
#define V_FIELD  5000
#define TOTALV   (FF * V_FIELD)     // 100000
#define DD       64
#define BB       8192
#define NPAIRS   190

#define WARPS_PER_BLOCK  2
#define NBLOCKS          (BB / WARPS_PER_BLOCK)  // 4096 -> finest wave granularity

// Sample-major single kernel (converged structure). One warp per sample walks
// ALL 190 pairs in fixed order; all 8192 warps in one wave -> temporal L2
// confinement keeps DRAM at the unique-row floor (~415MB) while L1<-L2 runs
// at the chip LTS cap (797MB @ ~6300 B/cyc = the measured 72us: this kernel
// is LTS-throughput-bound; R8/R11 proved more per-warp MLP only hurts).
// R12 change: ONLY CTA size 128 -> 64 (2 warps) for the finest scheduling /
// tail-drain quantum. Body, regs (32), unroll, __ldg all identical to R10.
__global__ void __launch_bounds__(WARPS_PER_BLOCK * 32)
ffm_all(const int* __restrict__ x, const float* __restrict__ W,
        const float* __restrict__ Wl, const float* __restrict__ bias,
        float* __restrict__ out) {
    // Pair metadata: {i, j, baseA, baseB}; bases in float2 units.
    __shared__ int4 meta[NPAIRS];
    for (int p = threadIdx.x; p < NPAIRS; p += blockDim.x) {
        int i = 0, rem = p;
        while (rem >= FF - 1 - i) { rem -= FF - 1 - i; i++; }
        const int j = i + 1 + rem;
        // a = W[j, i*V_FIELD + xi], b = W[i, j*V_FIELD + xj]
        meta[p] = make_int4(i, j,
                            (j * TOTALV + i * V_FIELD) * (DD / 2),
                            (i * TOTALV + j * V_FIELD) * (DD / 2));
    }
    __syncthreads();

    const int lane = threadIdx.x & 31;
    const int w    = threadIdx.x >> 5;
    const int s    = blockIdx.x * WARPS_PER_BLOCK + w;
    const float2* __restrict__ W2 = (const float2*)W;

    // Index row across lanes; lanes < FF seed the linear term, then the
    // index is pre-scaled to float2-row units (x32).
    int   xv  = 0;
    float acc = 0.f;
    if (lane < FF) {
        xv  = x[s * FF + lane];
        acc = __ldg(&Wl[lane * V_FIELD + xv]);
        xv *= (DD / 2);
    }

    #pragma unroll 5
    for (int q = 0; q < NPAIRS; q++) {
        const int4 m = meta[q];
        const int xi = __shfl_sync(0xffffffffu, xv, m.x);
        const int xj = __shfl_sync(0xffffffffu, xv, m.y);
        const float2 av = __ldg(W2 + (unsigned)(m.z + xi) + lane);
        const float2 bv = __ldg(W2 + (unsigned)(m.w + xj) + lane);
        acc = fmaf(av.x, bv.x, acc);
        acc = fmaf(av.y, bv.y, acc);
    }

    #pragma unroll
    for (int o = 16; o; o >>= 1)
        acc += __shfl_xor_sync(0xffffffffu, acc, o);
    if (lane == 0) {
        const float z = acc + bias[0];
        out[s] = 1.f / (1.f + __expf(-z));
    }
}

extern "C" void kernel_launch(void* const* d_in, const int* in_sizes, int n_in,
                              void* d_out, int out_size) {
    const int*   x    = (const int*)d_in[0];
    const float* W    = (const float*)d_in[1];
    const float* Wl   = (const float*)d_in[2];
    const float* bias = (const float*)d_in[3];
    float*       out  = (float*)d_out;

    ffm_all<<<NBLOCKS, WARPS_PER_BLOCK * 32>>>(x, W, Wl, bias, out);
}